// round 1
// baseline (speedup 1.0000x reference)
#include <cuda_runtime.h>
#include <math.h>

#define B 4
#define L 2048
#define DIM 512
#define H 8
#define D 64
#define M_TOTAL (B * L)       // 8192
#define SCALE 0.125f          // 64^-0.5
#define NEG_MASK -10000.0f

// Scratch (allocation-free rule: __device__ globals). 4 x 16 MB = 64 MB.
__device__ float g_q[M_TOTAL * DIM];
__device__ float g_k[M_TOTAL * DIM];
__device__ float g_v[M_TOTAL * DIM];
__device__ float g_o[M_TOTAL * DIM];

// ---------------------------------------------------------------------------
// Tiled GEMM: Y[m][n] = sum_k X[m][k] * W[n][k]   (torch Linear: x @ W.T)
// Block tile 64x64, K-tile 16, 256 threads, 4x4 micro-tile per thread.
// ---------------------------------------------------------------------------
__device__ __forceinline__ void gemm_xwT_body(const float* __restrict__ X,
                                              const float* __restrict__ W,
                                              float* __restrict__ Y) {
    __shared__ float As[64][17];
    __shared__ float Bs[64][17];

    const int tid = threadIdx.x;
    const int ty = tid >> 4, tx = tid & 15;
    const int m_block = blockIdx.y * 64;
    const int n_block = blockIdx.x * 64;
    const int m0 = ty * 4, n0 = tx * 4;

    float acc[4][4];
#pragma unroll
    for (int i = 0; i < 4; i++)
#pragma unroll
        for (int j = 0; j < 4; j++) acc[i][j] = 0.0f;

    for (int k0 = 0; k0 < DIM; k0 += 16) {
#pragma unroll
        for (int t = 0; t < 4; t++) {
            int idx = tid + t * 256;          // 0..1023
            int r = idx >> 4, c = idx & 15;
            As[r][c] = X[(size_t)(m_block + r) * DIM + k0 + c];
            Bs[r][c] = W[(size_t)(n_block + r) * DIM + k0 + c];
        }
        __syncthreads();
#pragma unroll
        for (int kk = 0; kk < 16; kk++) {
            float a[4], b[4];
#pragma unroll
            for (int i = 0; i < 4; i++) a[i] = As[m0 + i][kk];
#pragma unroll
            for (int j = 0; j < 4; j++) b[j] = Bs[n0 + j][kk];
#pragma unroll
            for (int i = 0; i < 4; i++)
#pragma unroll
                for (int j = 0; j < 4; j++)
                    acc[i][j] = fmaf(a[i], b[j], acc[i][j]);
        }
        __syncthreads();
    }

#pragma unroll
    for (int i = 0; i < 4; i++)
#pragma unroll
        for (int j = 0; j < 4; j++)
            Y[(size_t)(m_block + m0 + i) * DIM + n_block + n0 + j] = acc[i][j];
}

// QKV projections fused into one launch via blockIdx.z.
__global__ void qkv_kernel(const float* __restrict__ x,
                           const float* __restrict__ wq,
                           const float* __restrict__ wk,
                           const float* __restrict__ wv) {
    const float* W = (blockIdx.z == 0) ? wq : (blockIdx.z == 1) ? wk : wv;
    float* Y = (blockIdx.z == 0) ? g_q : (blockIdx.z == 1) ? g_k : g_v;
    gemm_xwT_body(x, W, Y);
}

// Output projection: out = g_o @ wo.T
__global__ void outproj_kernel(const float* __restrict__ wo,
                               float* __restrict__ out) {
    gemm_xwT_body(g_o, wo, out);
}

// ---------------------------------------------------------------------------
// Flash-attention with diagonal mask.
// grid: (L/64 q-tiles, B*H). block: 256 threads (16x16), 4x4 micro-tiles.
// smem: Qs[64][64] + Ks[64][65] (reused as P) + Vs[64][64] = 49408 B dynamic.
// ---------------------------------------------------------------------------
#define ATTN_SMEM ((4096 + 4160 + 4096) * (int)sizeof(float))

__global__ void attn_kernel() {
    extern __shared__ float sm[];
    float* Qs = sm;                    // [64][64]
    float* Ks = sm + 4096;             // [64][65]  (later holds P)
    float* Vs = sm + 4096 + 4160;      // [64][64]

    const int tid = threadIdx.x;
    const int ty = tid >> 4, tx = tid & 15;
    const int m0 = ty * 4;             // query rows within tile
    const int n0 = tx * 4;             // key cols / d cols within tile
    const int bh = blockIdx.y;
    const int b = bh >> 3, h = bh & 7;
    const int q0 = blockIdx.x * 64;

    const float* Qg = g_q + (size_t)b * L * DIM + (size_t)h * D;
    const float* Kg = g_k + (size_t)b * L * DIM + (size_t)h * D;
    const float* Vg = g_v + (size_t)b * L * DIM + (size_t)h * D;
    float* Og = g_o + (size_t)b * L * DIM + (size_t)h * D;

    // Load Q tile once.
#pragma unroll
    for (int t = 0; t < 16; t++) {
        int idx = tid + t * 256;       // 0..4095
        int r = idx >> 6, c = idx & 63;
        Qs[r * 64 + c] = Qg[(size_t)(q0 + r) * DIM + c];
    }

    float m_i[4], l_i[4], o[4][4];
#pragma unroll
    for (int i = 0; i < 4; i++) {
        m_i[i] = -1e30f;
        l_i[i] = 0.0f;
#pragma unroll
        for (int j = 0; j < 4; j++) o[i][j] = 0.0f;
    }

    for (int k0 = 0; k0 < L; k0 += 64) {
        // Load K,V tiles.
#pragma unroll
        for (int t = 0; t < 16; t++) {
            int idx = tid + t * 256;
            int r = idx >> 6, c = idx & 63;
            Ks[r * 65 + c] = Kg[(size_t)(k0 + r) * DIM + c];
            Vs[r * 64 + c] = Vg[(size_t)(k0 + r) * DIM + c];
        }
        __syncthreads();

        // S = Q K^T (4x4 per thread)
        float s[4][4];
#pragma unroll
        for (int i = 0; i < 4; i++)
#pragma unroll
            for (int j = 0; j < 4; j++) s[i][j] = 0.0f;
#pragma unroll 8
        for (int d = 0; d < 64; d++) {
            float a[4], kb[4];
#pragma unroll
            for (int i = 0; i < 4; i++) a[i] = Qs[(m0 + i) * 64 + d];
#pragma unroll
            for (int j = 0; j < 4; j++) kb[j] = Ks[(n0 + j) * 65 + d];
#pragma unroll
            for (int i = 0; i < 4; i++)
#pragma unroll
                for (int j = 0; j < 4; j++)
                    s[i][j] = fmaf(a[i], kb[j], s[i][j]);
        }

        // Scale + diagonal mask; online softmax (reduce across 16 lanes of tx).
#pragma unroll
        for (int i = 0; i < 4; i++) {
            int grow = q0 + m0 + i;
            float rmax = -1e30f;
#pragma unroll
            for (int j = 0; j < 4; j++) {
                float v = s[i][j] * SCALE;
                if (grow == k0 + n0 + j) v = NEG_MASK;
                s[i][j] = v;
                rmax = fmaxf(rmax, v);
            }
#pragma unroll
            for (int off = 8; off >= 1; off >>= 1)
                rmax = fmaxf(rmax, __shfl_xor_sync(0xffffffffu, rmax, off));

            float m_new = fmaxf(m_i[i], rmax);
            float corr = __expf(m_i[i] - m_new);
            m_i[i] = m_new;
            l_i[i] *= corr;
#pragma unroll
            for (int j = 0; j < 4; j++) o[i][j] *= corr;

            float rsum = 0.0f;
#pragma unroll
            for (int j = 0; j < 4; j++) {
                s[i][j] = __expf(s[i][j] - m_new);
                rsum += s[i][j];
            }
#pragma unroll
            for (int off = 8; off >= 1; off >>= 1)
                rsum += __shfl_xor_sync(0xffffffffu, rsum, off);
            l_i[i] += rsum;
        }
        __syncthreads();           // everyone done reading Ks

        // Write P over Ks.
#pragma unroll
        for (int i = 0; i < 4; i++)
#pragma unroll
            for (int j = 0; j < 4; j++)
                Ks[(m0 + i) * 65 + n0 + j] = s[i][j];
        __syncthreads();

        // O += P @ V   (thread: rows m0.., d-cols n0..)
#pragma unroll 8
        for (int kk = 0; kk < 64; kk++) {
            float p[4], vv[4];
#pragma unroll
            for (int i = 0; i < 4; i++) p[i] = Ks[(m0 + i) * 65 + kk];
#pragma unroll
            for (int j = 0; j < 4; j++) vv[j] = Vs[kk * 64 + n0 + j];
#pragma unroll
            for (int i = 0; i < 4; i++)
#pragma unroll
                for (int j = 0; j < 4; j++)
                    o[i][j] = fmaf(p[i], vv[j], o[i][j]);
        }
        __syncthreads();           // before next K/V load overwrites smem
    }

    // Normalize and store (layout [b, l, h*64 + d] so out-proj is a plain GEMM)
#pragma unroll
    for (int i = 0; i < 4; i++) {
        float inv = 1.0f / l_i[i];
#pragma unroll
        for (int j = 0; j < 4; j++)
            Og[(size_t)(q0 + m0 + i) * DIM + n0 + j] = o[i][j] * inv;
    }
}

// ---------------------------------------------------------------------------
extern "C" void kernel_launch(void* const* d_in, const int* in_sizes, int n_in,
                              void* d_out, int out_size) {
    const float* x  = (const float*)d_in[0];
    const float* wq = (const float*)d_in[1];
    const float* wk = (const float*)d_in[2];
    const float* wv = (const float*)d_in[3];
    const float* wo = (const float*)d_in[4];
    float* out = (float*)d_out;

    cudaFuncSetAttribute(attn_kernel,
                         cudaFuncAttributeMaxDynamicSharedMemorySize, ATTN_SMEM);

    dim3 blk(256);
    // QKV projections: [8192,512] x [512,512]^T, z selects q/k/v
    qkv_kernel<<<dim3(DIM / 64, M_TOTAL / 64, 3), blk>>>(x, wq, wk, wv);
    // Attention: 32 q-tiles x 32 (b,h)
    attn_kernel<<<dim3(L / 64, B * H), blk, ATTN_SMEM>>>();
    // Output projection
    outproj_kernel<<<dim3(DIM / 64, M_TOTAL / 64), blk>>>(wo, out);
}

// round 3
// speedup vs baseline: 3.7096x; 3.7096x over previous
#include <cuda_runtime.h>
#include <cstdint>

#define B 4
#define L 2048
#define DIM 512
#define H 8
#define D 64
#define M_TOTAL (B * L)
#define SCALE 0.125f

// Scratch: __device__ globals (allocation-free rule). 4 x 16 MB.
__device__ float g_q[M_TOTAL * DIM];
__device__ float g_k[M_TOTAL * DIM];
__device__ float g_v[M_TOTAL * DIM];
__device__ float g_o[M_TOTAL * DIM];

__device__ __forceinline__ uint32_t f2tf(float x) {
    uint32_t r;
    asm("cvt.rna.tf32.f32 %0, %1;" : "=r"(r) : "f"(x));
    return r;
}

__device__ __forceinline__ void mma_tf32(float* d, const uint32_t* a,
                                         const uint32_t* b) {
    asm volatile(
        "mma.sync.aligned.m16n8k8.row.col.f32.tf32.tf32.f32 "
        "{%0,%1,%2,%3}, {%4,%5,%6,%7}, {%8,%9}, {%0,%1,%2,%3};"
        : "+f"(d[0]), "+f"(d[1]), "+f"(d[2]), "+f"(d[3])
        : "r"(a[0]), "r"(a[1]), "r"(a[2]), "r"(a[3]), "r"(b[0]), "r"(b[1]));
}

// ---------------------------------------------------------------------------
// GEMM: Y[m][n] = sum_k X[m][k] * W[n][k]  (x @ W.T), tf32 mma.sync.
// Block 128x128, 256 threads = 8 warps (4 m x 2 n), warp tile 32x64, K-chunk 32.
// ---------------------------------------------------------------------------
#define PADG 36

__global__ __launch_bounds__(256, 2) void gemm_tc(const float* __restrict__ Xin,
                                                  const float* __restrict__ W,
                                                  float* __restrict__ Yin,
                                                  int vmode) {
    __shared__ uint32_t As[128 * PADG];
    __shared__ uint32_t Bs[128 * PADG];

    const int tid = threadIdx.x, lane = tid & 31, wid = tid >> 5;
    const int wm = wid & 3, wn = wid >> 2;
    const int mb = blockIdx.y * 128, nb = blockIdx.x * 128;

    const float* X = (vmode == 3) ? g_o : Xin;
    float* Y = (vmode == 0) ? g_q : (vmode == 1) ? g_k : (vmode == 2) ? g_v : Yin;

    float acc[2][8][4];
#pragma unroll
    for (int i = 0; i < 2; i++)
#pragma unroll
        for (int j = 0; j < 8; j++)
#pragma unroll
            for (int c = 0; c < 4; c++) acc[i][j][c] = 0.0f;

    const int lr = lane >> 2, lc = lane & 3;

    for (int kt = 0; kt < 16; kt++) {
        const int k0 = kt * 32;
#pragma unroll
        for (int t = 0; t < 4; t++) {
            int idx = tid + t * 256;           // 0..1023 float4s
            int r = idx >> 3, c4 = idx & 7;
            float4 xa = *(const float4*)(X + (size_t)(mb + r) * DIM + k0 + c4 * 4);
            float4 xb = *(const float4*)(W + (size_t)(nb + r) * DIM + k0 + c4 * 4);
            uint4 ua = make_uint4(f2tf(xa.x), f2tf(xa.y), f2tf(xa.z), f2tf(xa.w));
            uint4 ub = make_uint4(f2tf(xb.x), f2tf(xb.y), f2tf(xb.z), f2tf(xb.w));
            *(uint4*)(As + r * PADG + c4 * 4) = ua;
            *(uint4*)(Bs + r * PADG + c4 * 4) = ub;
        }
        __syncthreads();

#pragma unroll
        for (int ks = 0; ks < 4; ks++) {
            const int kk = ks * 8;
            uint32_t a[2][4], b[8][2];
#pragma unroll
            for (int mt = 0; mt < 2; mt++) {
                int r0 = wm * 32 + mt * 16 + lr;
                a[mt][0] = As[r0 * PADG + kk + lc];
                a[mt][1] = As[(r0 + 8) * PADG + kk + lc];
                a[mt][2] = As[r0 * PADG + kk + lc + 4];
                a[mt][3] = As[(r0 + 8) * PADG + kk + lc + 4];
            }
#pragma unroll
            for (int nt = 0; nt < 8; nt++) {
                int n0 = wn * 64 + nt * 8 + lr;
                b[nt][0] = Bs[n0 * PADG + kk + lc];
                b[nt][1] = Bs[n0 * PADG + kk + lc + 4];
            }
#pragma unroll
            for (int mt = 0; mt < 2; mt++)
#pragma unroll
                for (int nt = 0; nt < 8; nt++)
                    mma_tf32(acc[mt][nt], a[mt], b[nt]);
        }
        __syncthreads();
    }

    // Epilogue: D frag (mt,nt): rows wm*32+mt*16+lr (+8), cols wn*64+nt*8+2*lc (+1)
#pragma unroll
    for (int mt = 0; mt < 2; mt++) {
        int r0 = mb + wm * 32 + mt * 16 + lr;
#pragma unroll
        for (int nt = 0; nt < 8; nt++) {
            int c0 = nb + wn * 64 + nt * 8 + 2 * lc;
            *(float2*)(Y + (size_t)r0 * DIM + c0) =
                make_float2(acc[mt][nt][0], acc[mt][nt][1]);
            *(float2*)(Y + (size_t)(r0 + 8) * DIM + c0) =
                make_float2(acc[mt][nt][2], acc[mt][nt][3]);
        }
    }
}

// ---------------------------------------------------------------------------
// Flash attention, tf32 mma.sync, single-pass softmax (no running max).
// CTA: 128 q rows of one (b,h); key tile 64. 256 threads = 8 warps,
// warp w owns q rows [w*16, w*16+16).
//   smem: Qs[128][68] tf32, Ks[64][68] tf32 (reused for P[128][68]... P is
//         [128 q][64 key] -> needs 128 rows! see note), Vs[64][72] tf32.
// NOTE: P overlays Ks region; P rows are warp-local (each warp reads only its
// own 16 rows), Ks region sized for 128 rows.
// ---------------------------------------------------------------------------
#define PADQ 68
#define PADV 72
#define QS_WORDS (128 * PADQ)
#define KS_WORDS (128 * PADQ)   // holds K tile (64 rows used) and P (128 rows)
#define VS_WORDS (64 * PADV)
#define ATTN_SMEM ((QS_WORDS + KS_WORDS + VS_WORDS) * 4)

__global__ __launch_bounds__(256, 1) void attn_tc() {
    extern __shared__ uint32_t sm[];
    uint32_t* Qs = sm;
    uint32_t* Ks = sm + QS_WORDS;        // K tile / P tile
    uint32_t* Vs = sm + QS_WORDS + KS_WORDS;

    const int tid = threadIdx.x, lane = tid & 31, wid = tid >> 5;
    const int lr = lane >> 2, lc = lane & 3;
    const int bh = blockIdx.y, b_ = bh >> 3, h_ = bh & 7;
    const int q0 = blockIdx.x * 128;

    const float* Qg = g_q + (size_t)b_ * L * DIM + h_ * 64;
    const float* Kg = g_k + (size_t)b_ * L * DIM + h_ * 64;
    const float* Vg = g_v + (size_t)b_ * L * DIM + h_ * 64;

    // Load Q tile [128][64] as tf32.
#pragma unroll
    for (int t = 0; t < 8; t++) {
        int idx = tid + t * 256;             // 0..2047 float4s
        int r = idx >> 4, c4 = idx & 15;
        float4 x = *(const float4*)(Qg + (size_t)(q0 + r) * DIM + c4 * 4);
        *(uint4*)(Qs + r * PADQ + c4 * 4) =
            make_uint4(f2tf(x.x), f2tf(x.y), f2tf(x.z), f2tf(x.w));
    }
    __syncthreads();

    // Hoist Q fragments (stationary): 8 k-steps x 4 regs.
    uint32_t aq[8][4];
    {
        int r0 = wid * 16 + lr;
#pragma unroll
        for (int ks = 0; ks < 8; ks++) {
            int kk = ks * 8;
            aq[ks][0] = Qs[r0 * PADQ + kk + lc];
            aq[ks][1] = Qs[(r0 + 8) * PADQ + kk + lc];
            aq[ks][2] = Qs[r0 * PADQ + kk + lc + 4];
            aq[ks][3] = Qs[(r0 + 8) * PADQ + kk + lc + 4];
        }
    }

    float o[8][4];
#pragma unroll
    for (int nt = 0; nt < 8; nt++)
#pragma unroll
        for (int c = 0; c < 4; c++) o[nt][c] = 0.0f;
    float l0 = 0.0f, l1 = 0.0f;

    const int row0 = q0 + wid * 16 + lr;     // global q row for c0/c1
    const int row1 = row0 + 8;               // for c2/c3

    for (int t = 0; t < 32; t++) {
        const int k0g = t * 64;
        // Load K [64][64] and V [64][64] tiles as tf32.
#pragma unroll
        for (int u = 0; u < 4; u++) {
            int idx = tid + u * 256;         // 0..1023 float4s
            int r = idx >> 4, c4 = idx & 15;
            float4 xk = *(const float4*)(Kg + (size_t)(k0g + r) * DIM + c4 * 4);
            float4 xv = *(const float4*)(Vg + (size_t)(k0g + r) * DIM + c4 * 4);
            *(uint4*)(Ks + r * PADQ + c4 * 4) =
                make_uint4(f2tf(xk.x), f2tf(xk.y), f2tf(xk.z), f2tf(xk.w));
            *(uint4*)(Vs + r * PADV + c4 * 4) =
                make_uint4(f2tf(xv.x), f2tf(xv.y), f2tf(xv.z), f2tf(xv.w));
        }
        __syncthreads();

        // S = Q @ K^T : warp computes 16 q x 64 keys.
        float s[8][4];
#pragma unroll
        for (int nt = 0; nt < 8; nt++)
#pragma unroll
            for (int c = 0; c < 4; c++) s[nt][c] = 0.0f;
#pragma unroll
        for (int ks = 0; ks < 8; ks++) {
            const int kk = ks * 8;
            uint32_t bkf[8][2];
#pragma unroll
            for (int nt = 0; nt < 8; nt++) {
                int key = nt * 8 + lr;
                bkf[nt][0] = Ks[key * PADQ + kk + lc];
                bkf[nt][1] = Ks[key * PADQ + kk + lc + 4];
            }
#pragma unroll
            for (int nt = 0; nt < 8; nt++) mma_tf32(s[nt], aq[ks], bkf[nt]);
        }
        __syncthreads();    // all warps done reading Ks before P overwrite

        // Softmax piece: p = exp(s*SCALE), diag -> 0; write P (tf32) over Ks.
        {
            int prow0 = wid * 16 + lr;
#pragma unroll
            for (int nt = 0; nt < 8; nt++) {
                int key = k0g + nt * 8 + 2 * lc;
                float p0 = __expf(s[nt][0] * SCALE);
                float p1 = __expf(s[nt][1] * SCALE);
                float p2 = __expf(s[nt][2] * SCALE);
                float p3 = __expf(s[nt][3] * SCALE);
                if (key == row0) p0 = 0.0f;
                if (key + 1 == row0) p1 = 0.0f;
                if (key == row1) p2 = 0.0f;
                if (key + 1 == row1) p3 = 0.0f;
                l0 += p0 + p1;
                l1 += p2 + p3;
                int cc = nt * 8 + 2 * lc;
                *(uint2*)(Ks + prow0 * PADQ + cc) =
                    make_uint2(f2tf(p0), f2tf(p1));
                *(uint2*)(Ks + (prow0 + 8) * PADQ + cc) =
                    make_uint2(f2tf(p2), f2tf(p3));
            }
        }
        __syncwarp();   // P rows are warp-local; warp-level ordering suffices

        // O += P @ V : A = P (warp rows), B = V (col-major over keys).
#pragma unroll
        for (int ks = 0; ks < 8; ks++) {
            const int kk = ks * 8;
            uint32_t ap[4];
            int r0 = wid * 16 + lr;
            ap[0] = Ks[r0 * PADQ + kk + lc];
            ap[1] = Ks[(r0 + 8) * PADQ + kk + lc];
            ap[2] = Ks[r0 * PADQ + kk + lc + 4];
            ap[3] = Ks[(r0 + 8) * PADQ + kk + lc + 4];
            uint32_t bv[8][2];
#pragma unroll
            for (int nt = 0; nt < 8; nt++) {
                int d0 = nt * 8 + lr;
                bv[nt][0] = Vs[(kk + lc) * PADV + d0];
                bv[nt][1] = Vs[(kk + lc + 4) * PADV + d0];
            }
#pragma unroll
            for (int nt = 0; nt < 8; nt++) mma_tf32(o[nt], ap, bv[nt]);
        }
        __syncthreads();    // before next tile load overwrites Ks/Vs
    }

    // Row sums: reduce over the 4 lanes of each quad.
#pragma unroll
    for (int off = 1; off <= 2; off <<= 1) {
        l0 += __shfl_xor_sync(0xffffffffu, l0, off);
        l1 += __shfl_xor_sync(0xffffffffu, l1, off);
    }
    const float inv0 = 1.0f / l0, inv1 = 1.0f / l1;

    // Write O to g_o[b, row, h*64 + d].
    float* Og = g_o + ((size_t)b_ * L) * DIM + h_ * 64;
#pragma unroll
    for (int nt = 0; nt < 8; nt++) {
        int c0 = nt * 8 + 2 * lc;
        *(float2*)(Og + (size_t)row0 * DIM + c0) =
            make_float2(o[nt][0] * inv0, o[nt][1] * inv0);
        *(float2*)(Og + (size_t)row1 * DIM + c0) =
            make_float2(o[nt][2] * inv1, o[nt][3] * inv1);
    }
}

// ---------------------------------------------------------------------------
extern "C" void kernel_launch(void* const* d_in, const int* in_sizes, int n_in,
                              void* d_out, int out_size) {
    const float* x  = (const float*)d_in[0];
    const float* wq = (const float*)d_in[1];
    const float* wk = (const float*)d_in[2];
    const float* wv = (const float*)d_in[3];
    const float* wo = (const float*)d_in[4];
    float* out = (float*)d_out;

    cudaFuncSetAttribute(attn_tc, cudaFuncAttributeMaxDynamicSharedMemorySize,
                         ATTN_SMEM);

    dim3 blk(256);
    dim3 gg(DIM / 128, M_TOTAL / 128);   // 4 x 64
    gemm_tc<<<gg, blk>>>(x, wq, nullptr, 0);
    gemm_tc<<<gg, blk>>>(x, wk, nullptr, 1);
    gemm_tc<<<gg, blk>>>(x, wv, nullptr, 2);
    attn_tc<<<dim3(L / 128, B * H), blk, ATTN_SMEM>>>();
    gemm_tc<<<gg, blk>>>(nullptr, wo, out, 3);
}

// round 4
// speedup vs baseline: 4.1085x; 1.1075x over previous
#include <cuda_runtime.h>
#include <cstdint>

#define B 4
#define L 2048
#define DIM 512
#define H 8
#define D 64
#define M_TOTAL (B * L)
#define SCALE 0.125f

// Scratch: __device__ globals (allocation-free rule). 4 x 16 MB.
__device__ float g_q[M_TOTAL * DIM];
__device__ float g_k[M_TOTAL * DIM];
__device__ float g_v[M_TOTAL * DIM];
__device__ float g_o[M_TOTAL * DIM];

__device__ __forceinline__ uint32_t f2tf(float x) {
    uint32_t r;
    asm("cvt.rna.tf32.f32 %0, %1;" : "=r"(r) : "f"(x));
    return r;
}

__device__ __forceinline__ void mma_tf32(float* d, const uint32_t* a,
                                         const uint32_t* b) {
    asm volatile(
        "mma.sync.aligned.m16n8k8.row.col.f32.tf32.tf32.f32 "
        "{%0,%1,%2,%3}, {%4,%5,%6,%7}, {%8,%9}, {%0,%1,%2,%3};"
        : "+f"(d[0]), "+f"(d[1]), "+f"(d[2]), "+f"(d[3])
        : "r"(a[0]), "r"(a[1]), "r"(a[2]), "r"(a[3]), "r"(b[0]), "r"(b[1]));
}

// ---------------------------------------------------------------------------
// GEMM body: Y[m][n] = sum_k X[m][k]*W[n][k] (x @ W.T), tf32 mma.sync.
// Block 128x128, 256 threads = 8 warps (4m x 2n), warp tile 32x64, K-chunk 32.
// ---------------------------------------------------------------------------
#define PADG 36

__device__ __forceinline__ void gemm_body(const float* __restrict__ X,
                                          const float* __restrict__ W,
                                          float* __restrict__ Y) {
    __shared__ uint32_t As[128 * PADG];
    __shared__ uint32_t Bs[128 * PADG];

    const int tid = threadIdx.x, lane = tid & 31, wid = tid >> 5;
    const int wm = wid & 3, wn = wid >> 2;
    const int mb = blockIdx.y * 128, nb = blockIdx.x * 128;
    const int lr = lane >> 2, lc = lane & 3;

    float acc[2][8][4];
#pragma unroll
    for (int i = 0; i < 2; i++)
#pragma unroll
        for (int j = 0; j < 8; j++)
#pragma unroll
            for (int c = 0; c < 4; c++) acc[i][j][c] = 0.0f;

    for (int kt = 0; kt < 16; kt++) {
        const int k0 = kt * 32;
#pragma unroll
        for (int t = 0; t < 4; t++) {
            int idx = tid + t * 256;
            int r = idx >> 3, c4 = idx & 7;
            float4 xa = *(const float4*)(X + (size_t)(mb + r) * DIM + k0 + c4 * 4);
            float4 xb = *(const float4*)(W + (size_t)(nb + r) * DIM + k0 + c4 * 4);
            *(uint4*)(As + r * PADG + c4 * 4) =
                make_uint4(f2tf(xa.x), f2tf(xa.y), f2tf(xa.z), f2tf(xa.w));
            *(uint4*)(Bs + r * PADG + c4 * 4) =
                make_uint4(f2tf(xb.x), f2tf(xb.y), f2tf(xb.z), f2tf(xb.w));
        }
        __syncthreads();

#pragma unroll
        for (int ks = 0; ks < 4; ks++) {
            const int kk = ks * 8;
            uint32_t a[2][4], b[8][2];
#pragma unroll
            for (int mt = 0; mt < 2; mt++) {
                int r0 = wm * 32 + mt * 16 + lr;
                a[mt][0] = As[r0 * PADG + kk + lc];
                a[mt][1] = As[(r0 + 8) * PADG + kk + lc];
                a[mt][2] = As[r0 * PADG + kk + lc + 4];
                a[mt][3] = As[(r0 + 8) * PADG + kk + lc + 4];
            }
#pragma unroll
            for (int nt = 0; nt < 8; nt++) {
                int n0 = wn * 64 + nt * 8 + lr;
                b[nt][0] = Bs[n0 * PADG + kk + lc];
                b[nt][1] = Bs[n0 * PADG + kk + lc + 4];
            }
#pragma unroll
            for (int mt = 0; mt < 2; mt++)
#pragma unroll
                for (int nt = 0; nt < 8; nt++)
                    mma_tf32(acc[mt][nt], a[mt], b[nt]);
        }
        __syncthreads();
    }

#pragma unroll
    for (int mt = 0; mt < 2; mt++) {
        int r0 = mb + wm * 32 + mt * 16 + lr;
#pragma unroll
        for (int nt = 0; nt < 8; nt++) {
            int c0 = nb + wn * 64 + nt * 8 + 2 * lc;
            *(float2*)(Y + (size_t)r0 * DIM + c0) =
                make_float2(acc[mt][nt][0], acc[mt][nt][1]);
            *(float2*)(Y + (size_t)(r0 + 8) * DIM + c0) =
                make_float2(acc[mt][nt][2], acc[mt][nt][3]);
        }
    }
}

__global__ __launch_bounds__(256, 2) void qkv_gemm(const float* __restrict__ x,
                                                   const float* __restrict__ wq,
                                                   const float* __restrict__ wk,
                                                   const float* __restrict__ wv) {
    const float* W = (blockIdx.z == 0) ? wq : (blockIdx.z == 1) ? wk : wv;
    float* Y = (blockIdx.z == 0) ? g_q : (blockIdx.z == 1) ? g_k : g_v;
    gemm_body(x, W, Y);
}

__global__ __launch_bounds__(256, 2) void out_gemm(const float* __restrict__ wo,
                                                   float* __restrict__ out) {
    gemm_body(g_o, wo, out);
}

// ---------------------------------------------------------------------------
// Flash attention, tf32 mma.sync, single-pass softmax, P kept in registers
// (shuffle-based D->A fragment relayout), key-split warp pairs.
// CTA: 128 q rows of one (b,h); key tile 64; 512 threads = 16 warps.
//   warp w: wq = w>>1 owns q rows [wq*16, wq*16+16); wk = w&1 owns keys
//   [wk*32, wk*32+32) of each 64-key tile. Final O/l merged via smem.
// smem: Qs[128][68] (reused as merge buffer), Ks[64][68], Vs[64][72].
// ---------------------------------------------------------------------------
#define PADQ 68
#define PADV 72
#define QS_WORDS (128 * PADQ)
#define KS_WORDS (64 * PADQ)
#define VS_WORDS (64 * PADV)
#define ATTN_SMEM ((QS_WORDS + KS_WORDS + VS_WORDS) * 4)

__global__ __launch_bounds__(512, 1) void attn_tc() {
    extern __shared__ uint32_t sm[];
    uint32_t* Qs = sm;                       // later: merge buffer
    uint32_t* Ks = sm + QS_WORDS;
    uint32_t* Vs = sm + QS_WORDS + KS_WORDS;

    const int tid = threadIdx.x, lane = tid & 31, wid = tid >> 5;
    const int lr = lane >> 2, lc = lane & 3;
    const int wq_ = wid >> 1;                // q group 0..7
    const int wk_ = wid & 1;                 // key half 0..1
    const int bh = blockIdx.y, b_ = bh >> 3, h_ = bh & 7;
    const int q0 = blockIdx.x * 128;

    const float* Qg = g_q + (size_t)b_ * L * DIM + h_ * 64;
    const float* Kg = g_k + (size_t)b_ * L * DIM + h_ * 64;
    const float* Vg = g_v + (size_t)b_ * L * DIM + h_ * 64;

    // Load Q tile [128][64] as tf32.
#pragma unroll
    for (int t = 0; t < 4; t++) {
        int idx = tid + t * 512;             // 0..2047 float4s
        int r = idx >> 4, c4 = idx & 15;
        float4 x = *(const float4*)(Qg + (size_t)(q0 + r) * DIM + c4 * 4);
        *(uint4*)(Qs + r * PADQ + c4 * 4) =
            make_uint4(f2tf(x.x), f2tf(x.y), f2tf(x.z), f2tf(x.w));
    }
    __syncthreads();

    // Hoist Q fragments (stationary across the key loop).
    uint32_t aq[8][4];
    {
        int r0 = wq_ * 16 + lr;
#pragma unroll
        for (int ks = 0; ks < 8; ks++) {
            int kk = ks * 8;
            aq[ks][0] = Qs[r0 * PADQ + kk + lc];
            aq[ks][1] = Qs[(r0 + 8) * PADQ + kk + lc];
            aq[ks][2] = Qs[r0 * PADQ + kk + lc + 4];
            aq[ks][3] = Qs[(r0 + 8) * PADQ + kk + lc + 4];
        }
    }
    __syncthreads();   // Qs free for reuse after this (merge buffer at end)

    float o[8][4];
#pragma unroll
    for (int nt = 0; nt < 8; nt++)
#pragma unroll
        for (int c = 0; c < 4; c++) o[nt][c] = 0.0f;
    float l0 = 0.0f, l1 = 0.0f;

    const int row0 = q0 + wq_ * 16 + lr;
    const int row1 = row0 + 8;
    const int src1 = (lane & 28) | (lc >> 1);   // D->A relayout source lanes
    const int src2 = src1 + 2;
    const bool oddc = (lc & 1);

    for (int t = 0; t < 32; t++) {
        const int k0g = t * 64;
        // Load K [64][64], V [64][64] as tf32.
#pragma unroll
        for (int u = 0; u < 2; u++) {
            int idx = tid + u * 512;          // 0..1023 float4s
            int r = idx >> 4, c4 = idx & 15;
            float4 xk = *(const float4*)(Kg + (size_t)(k0g + r) * DIM + c4 * 4);
            float4 xv = *(const float4*)(Vg + (size_t)(k0g + r) * DIM + c4 * 4);
            *(uint4*)(Ks + r * PADQ + c4 * 4) =
                make_uint4(f2tf(xk.x), f2tf(xk.y), f2tf(xk.z), f2tf(xk.w));
            *(uint4*)(Vs + r * PADV + c4 * 4) =
                make_uint4(f2tf(xv.x), f2tf(xv.y), f2tf(xv.z), f2tf(xv.w));
        }
        __syncthreads();

        // S = Q @ K^T : warp computes 16 q x its 32 keys (4 key tiles).
        float s[4][4];
#pragma unroll
        for (int nt = 0; nt < 4; nt++)
#pragma unroll
            for (int c = 0; c < 4; c++) s[nt][c] = 0.0f;
#pragma unroll
        for (int ks = 0; ks < 8; ks++) {
            const int kk = ks * 8;
            uint32_t bkf[4][2];
#pragma unroll
            for (int nt = 0; nt < 4; nt++) {
                int key = wk_ * 32 + nt * 8 + lr;
                bkf[nt][0] = Ks[key * PADQ + kk + lc];
                bkf[nt][1] = Ks[key * PADQ + kk + lc + 4];
            }
#pragma unroll
            for (int nt = 0; nt < 4; nt++) mma_tf32(s[nt], aq[ks], bkf[nt]);
        }

        // p = exp(s*SCALE); diagonal -> 0; accumulate row sums.
#pragma unroll
        for (int nt = 0; nt < 4; nt++) {
            int key = k0g + wk_ * 32 + nt * 8 + 2 * lc;
            float p0 = __expf(s[nt][0] * SCALE);
            float p1 = __expf(s[nt][1] * SCALE);
            float p2 = __expf(s[nt][2] * SCALE);
            float p3 = __expf(s[nt][3] * SCALE);
            if (key == row0) p0 = 0.0f;
            if (key + 1 == row0) p1 = 0.0f;
            if (key == row1) p2 = 0.0f;
            if (key + 1 == row1) p3 = 0.0f;
            l0 += p0 + p1;
            l1 += p2 + p3;
            s[nt][0] = p0; s[nt][1] = p1; s[nt][2] = p2; s[nt][3] = p3;
        }

        // O += P @ V, P fragments built from s via warp shuffles.
#pragma unroll
        for (int ksl = 0; ksl < 4; ksl++) {
            float e0 = __shfl_sync(0xffffffffu, s[ksl][0], src1);
            float e1 = __shfl_sync(0xffffffffu, s[ksl][1], src1);
            float e2 = __shfl_sync(0xffffffffu, s[ksl][2], src1);
            float e3 = __shfl_sync(0xffffffffu, s[ksl][3], src1);
            float f0 = __shfl_sync(0xffffffffu, s[ksl][0], src2);
            float f1 = __shfl_sync(0xffffffffu, s[ksl][1], src2);
            float f2 = __shfl_sync(0xffffffffu, s[ksl][2], src2);
            float f3 = __shfl_sync(0xffffffffu, s[ksl][3], src2);
            uint32_t ap[4];
            ap[0] = f2tf(oddc ? e1 : e0);
            ap[1] = f2tf(oddc ? e3 : e2);
            ap[2] = f2tf(oddc ? f1 : f0);
            ap[3] = f2tf(oddc ? f3 : f2);

            const int kk = wk_ * 32 + ksl * 8;
            uint32_t bv[8][2];
#pragma unroll
            for (int nt = 0; nt < 8; nt++) {
                int d0 = nt * 8 + lr;
                bv[nt][0] = Vs[(kk + lc) * PADV + d0];
                bv[nt][1] = Vs[(kk + lc + 4) * PADV + d0];
            }
#pragma unroll
            for (int nt = 0; nt < 8; nt++) mma_tf32(o[nt], ap, bv[nt]);
        }
        __syncthreads();   // before next tile load overwrites Ks/Vs
    }

    // Merge the two key-half warps of each pair via smem (Qs region reused).
    float* OS = (float*)sm;                        // [8 wq][32 lane][32]
    float* LS = (float*)(sm + QS_WORDS);           // [8 wq][32 lane][2]
    if (wk_ == 1) {
        float* dst = OS + ((size_t)wq_ * 32 + lane) * 32;
#pragma unroll
        for (int nt = 0; nt < 8; nt++)
#pragma unroll
            for (int c = 0; c < 4; c++) dst[nt * 4 + c] = o[nt][c];
        LS[(wq_ * 32 + lane) * 2 + 0] = l0;
        LS[(wq_ * 32 + lane) * 2 + 1] = l1;
    }
    __syncthreads();
    if (wk_ == 0) {
        const float* srcp = OS + ((size_t)wq_ * 32 + lane) * 32;
#pragma unroll
        for (int nt = 0; nt < 8; nt++)
#pragma unroll
            for (int c = 0; c < 4; c++) o[nt][c] += srcp[nt * 4 + c];
        l0 += LS[(wq_ * 32 + lane) * 2 + 0];
        l1 += LS[(wq_ * 32 + lane) * 2 + 1];
#pragma unroll
        for (int off = 1; off <= 2; off <<= 1) {
            l0 += __shfl_xor_sync(0xffffffffu, l0, off);
            l1 += __shfl_xor_sync(0xffffffffu, l1, off);
        }
        const float inv0 = 1.0f / l0, inv1 = 1.0f / l1;
        float* Og = g_o + ((size_t)b_ * L) * DIM + h_ * 64;
#pragma unroll
        for (int nt = 0; nt < 8; nt++) {
            int c0 = nt * 8 + 2 * lc;
            *(float2*)(Og + (size_t)row0 * DIM + c0) =
                make_float2(o[nt][0] * inv0, o[nt][1] * inv0);
            *(float2*)(Og + (size_t)row1 * DIM + c0) =
                make_float2(o[nt][2] * inv1, o[nt][3] * inv1);
        }
    }
}

// ---------------------------------------------------------------------------
extern "C" void kernel_launch(void* const* d_in, const int* in_sizes, int n_in,
                              void* d_out, int out_size) {
    const float* x  = (const float*)d_in[0];
    const float* wq = (const float*)d_in[1];
    const float* wk = (const float*)d_in[2];
    const float* wv = (const float*)d_in[3];
    const float* wo = (const float*)d_in[4];
    float* out = (float*)d_out;

    cudaFuncSetAttribute(attn_tc, cudaFuncAttributeMaxDynamicSharedMemorySize,
                         ATTN_SMEM);

    dim3 gg(DIM / 128, M_TOTAL / 128);       // 4 x 64
    qkv_gemm<<<dim3(4, 64, 3), 256>>>(x, wq, wk, wv);
    attn_tc<<<dim3(L / 128, B * H), 512, ATTN_SMEM>>>();
    out_gemm<<<gg, 256>>>(wo, out);
}